// round 16
// baseline (speedup 1.0000x reference)
#include <cuda_runtime.h>
#include <cuda_fp16.h>

#define N_NODES 65536
#define K_NBR   32
#define IN_DIM  128
#define D_DIM   64
#define OUT_C   95   // 31 row + 64 col

#define GRID2   608                 // 4 blocks/SM x 152 SMs = one full wave
#define WARPS2  8
#define NWARPS2 (GRID2 * WARPS2)    // 4864

// ---------------- device scratch (no cudaMalloc allowed) ----------------
__device__ __half2 g_zh[N_NODES * 32];        // z in fp16, 8 MB (col path)
__device__ float4  g_sp[N_NODES];             // {e_src, p0, p1, 0}
__device__ float   g_edst[N_NODES];
__device__ double  g_stats[4];                // row_sum, row_ss, col_sum, col_ss
__device__ float4  g_bn;                      // {rscale, rbias, cscale, cbias}
__device__ unsigned g_ticket;                 // last-block detector
__device__ unsigned g_flag;                   // BN-ready release flag

// ---------------- f32x2 packed helpers (sm_103a) ----------------
__device__ __forceinline__ unsigned long long pack2(float lo, float hi) {
    unsigned long long r;
    asm("mov.b64 %0,{%1,%2};" : "=l"(r) : "f"(lo), "f"(hi));
    return r;
}
__device__ __forceinline__ unsigned long long fma2(unsigned long long a,
                                                   unsigned long long b,
                                                   unsigned long long c) {
    unsigned long long d;
    asm("fma.rn.f32x2 %0,%1,%2,%3;" : "=l"(d) : "l"(a), "l"(b), "l"(c));
    return d;
}
__device__ __forceinline__ float2 unpack2(unsigned long long v) {
    float2 f;
    asm("mov.b64 {%0,%1},%2;" : "=f"(f.x), "=f"(f.y) : "l"(v));
    return f;
}

#define WSTRIDE 68   // w_s row stride (pad: transpose-write conflicts <=4-way)

// =========================================================================
// Kernel 1: z = h @ W_fc^T with packed f32x2 FMA. 32 rows/block.
// Transposes W from global itself; block 0 zeroes stats/ticket/flag.
// (round-12 verbatim)
// =========================================================================
__global__ __launch_bounds__(128) void k1_gemm(
    const float* __restrict__ h,
    const float* __restrict__ W,       // [64,128] row-major
    const float* __restrict__ a_attn,  // [128]
    const float* __restrict__ w_row)   // [2,64]
{
    extern __shared__ float smem[];
    float* w_s = smem;                       // [128][WSTRIDE]
    float* h_s = smem + 128 * WSTRIDE;       // [128][34]

    const int t    = threadIdx.x;
    const int base = blockIdx.x * 32;

    if (blockIdx.x == 0) {
        if (t < 4) g_stats[t] = 0.0;
        if (t == 4) g_ticket = 0u;
        if (t == 5) g_flag = 0u;
    }

    #pragma unroll
    for (int idx = t; idx < 64 * 128; idx += 128) {
        int d = idx >> 7, i = idx & 127;
        w_s[i * WSTRIDE + d] = W[idx];
    }

    #pragma unroll
    for (int idx = t; idx < 32 * 128; idx += 128) {
        int r = idx >> 7, c = idx & 127;
        h_s[c * 34 + r] = h[(size_t)(base + r) * IN_DIM + c];
    }
    __syncthreads();

    const int cg = t & 15;
    const int rg = t >> 4;
    const int r0 = rg * 4;

    unsigned long long accA[4] = {0, 0, 0, 0};
    unsigned long long accB[4] = {0, 0, 0, 0};

    #pragma unroll 8
    for (int k = 0; k < 128; k++) {
        float4 w = *(const float4*)&w_s[k * WSTRIDE + cg * 4];
        unsigned long long hA = *(const unsigned long long*)&h_s[k * 34 + r0];
        unsigned long long hB = *(const unsigned long long*)&h_s[k * 34 + r0 + 2];
        unsigned long long w0 = pack2(w.x, w.x);
        unsigned long long w1 = pack2(w.y, w.y);
        unsigned long long w2 = pack2(w.z, w.z);
        unsigned long long w3 = pack2(w.w, w.w);
        accA[0] = fma2(w0, hA, accA[0]);  accB[0] = fma2(w0, hB, accB[0]);
        accA[1] = fma2(w1, hA, accA[1]);  accB[1] = fma2(w1, hB, accB[1]);
        accA[2] = fma2(w2, hA, accA[2]);  accB[2] = fma2(w2, hB, accB[2]);
        accA[3] = fma2(w3, hA, accA[3]);  accB[3] = fma2(w3, hB, accB[3]);
    }

    float rv[4][4];
    #pragma unroll
    for (int j = 0; j < 4; j++) {
        float2 uA = unpack2(accA[j]);
        float2 uB = unpack2(accB[j]);
        rv[0][j] = uA.x; rv[1][j] = uA.y;
        rv[2][j] = uB.x; rv[3][j] = uB.y;
    }

    #pragma unroll
    for (int r = 0; r < 4; r++) {
        int n = base + r0 + r;
        __half2 p0 = __floats2half2_rn(rv[r][0], rv[r][1]);
        __half2 p1 = __floats2half2_rn(rv[r][2], rv[r][3]);
        uint2 pk = make_uint2(*(unsigned*)&p0, *(unsigned*)&p1);
        *(uint2*)&g_zh[(size_t)n * 32 + cg * 2] = pk;
    }

    float4 va0 = *(const float4*)&a_attn[cg * 4];
    float4 va1 = *(const float4*)&a_attn[64 + cg * 4];
    float4 vw0 = *(const float4*)&w_row[cg * 4];
    float4 vw1 = *(const float4*)&w_row[64 + cg * 4];

    float ps[16];
    #pragma unroll
    for (int r = 0; r < 4; r++) {
        ps[r*4+0] = rv[r][0]*va0.x + rv[r][1]*va0.y + rv[r][2]*va0.z + rv[r][3]*va0.w;
        ps[r*4+1] = rv[r][0]*va1.x + rv[r][1]*va1.y + rv[r][2]*va1.z + rv[r][3]*va1.w;
        ps[r*4+2] = rv[r][0]*vw0.x + rv[r][1]*vw0.y + rv[r][2]*vw0.z + rv[r][3]*vw0.w;
        ps[r*4+3] = rv[r][0]*vw1.x + rv[r][1]*vw1.y + rv[r][2]*vw1.z + rv[r][3]*vw1.w;
    }
    #pragma unroll
    for (int off = 8; off; off >>= 1) {
        #pragma unroll
        for (int j = 0; j < 16; j++)
            ps[j] += __shfl_down_sync(0xffffffffu, ps[j], off, 16);
    }
    if (cg == 0) {
        #pragma unroll
        for (int r = 0; r < 4; r++) {
            int n = base + r0 + r;
            g_sp[n]   = make_float4(ps[r*4+0], ps[r*4+2], ps[r*4+3], 0.f);
            g_edst[n] = ps[r*4+1];
        }
    }
}

// =========================================================================
// Kernel 2 (fused, persistent single wave). Round-14 config (best).
// Single change: phase-2 BN re-walks nodes with the known per-node layout
// (no modulo, no selects) -> ~16 instr/node instead of ~116.
// =========================================================================
__global__ __launch_bounds__(256, 4) void k2_fused(
    const int*   __restrict__ src_idx,
    const float* __restrict__ w_col,    // [32,64]
    const float* __restrict__ b_row_p,
    const float* __restrict__ b_col_p,
    const float* __restrict__ g_row,
    const float* __restrict__ beta_row,
    const float* __restrict__ g_col,
    const float* __restrict__ beta_col,
    float*       __restrict__ out)
{
    __shared__ __align__(16) __half2 wc_h[K_NBR * 32];  // [kk][lane], 4 KB
    __shared__ float red_s[4][WARPS2];
    __shared__ float4 bn_sh;

    const int t = threadIdx.x;
    const float2* wcg = (const float2*)w_col;
    #pragma unroll
    for (int i = t; i < K_NBR * 32; i += 256) {
        float2 w2 = wcg[i];
        wc_h[i] = __floats2half2_rn(w2.x, w2.y);
    }
    __syncthreads();

    const int lane = t & 31;
    const int wid  = t >> 5;
    const float b_row = b_row_p[0];
    const float b_col = b_col_p[0];

    float rs = 0.f, rss = 0.f, cs = 0.f, css = 0.f;

    const int warp_global = blockIdx.x * WARPS2 + wid;

    for (int n = warp_global; n < N_NODES; n += NWARPS2) {
        const int s = src_idx[n * K_NBR + lane];
        const float4 sp = g_sp[s];                    // {e_src, p0, p1, _}
        float e = sp.x + g_edst[n];
        e = fmaxf(e, 0.f) + 0.01f * fminf(e, 0.f);    // leaky relu

        // softmax without max-shift: |e| bounded (~6), exp fp32-safe
        float ex = __expf(e);
        float sum = ex;
        #pragma unroll
        for (int o = 16; o; o >>= 1) sum += __shfl_xor_sync(0xffffffffu, sum, o);
        const float alpha = __fdividef(ex, sum);

        // row conv
        float t0  = alpha * sp.y;
        float t1  = alpha * sp.z;
        float t1n = __shfl_down_sync(0xffffffffu, t1, 1);
        if (lane < 31) {
            float rv = t0 + t1n + b_row;
            out[(size_t)n * OUT_C + lane] = rv;
            rs += rv; rss += rv * rv;
        }

        // col conv: half2 product z*w (HMUL2), fp32 alpha*acc
        float2 acc = make_float2(0.f, 0.f);
        #pragma unroll 8
        for (int kk = 0; kk < K_NBR; kk++) {
            float a_k = __shfl_sync(0xffffffffu, alpha, kk);
            int   s_k = __shfl_sync(0xffffffffu, s, kk);
            __half2 zh = g_zh[(size_t)s_k * 32 + lane];
            __half2 pw = __hmul2(zh, wc_h[kk * 32 + lane]);
            float2 pf = __half22float2(pw);
            acc.x = fmaf(a_k, pf.x, acc.x);
            acc.y = fmaf(a_k, pf.y, acc.y);
        }
        float c0 = acc.x + b_col, c1 = acc.y + b_col;
        size_t ob = (size_t)n * OUT_C + 31 + lane * 2;
        out[ob]     = c0;
        out[ob + 1] = c1;
        cs  += c0 + c1;
        css += c0 * c0 + c1 * c1;
    }

    // ---- block-reduce stats ----
    #pragma unroll
    for (int o = 16; o; o >>= 1) {
        rs  += __shfl_xor_sync(0xffffffffu, rs,  o);
        rss += __shfl_xor_sync(0xffffffffu, rss, o);
        cs  += __shfl_xor_sync(0xffffffffu, cs,  o);
        css += __shfl_xor_sync(0xffffffffu, css, o);
    }
    if (lane == 0) {
        red_s[0][wid] = rs; red_s[1][wid] = rss;
        red_s[2][wid] = cs; red_s[3][wid] = css;
    }
    __syncthreads();
    if (t == 0) {
        double a0 = 0, a1 = 0, a2 = 0, a3 = 0;
        #pragma unroll
        for (int w = 0; w < WARPS2; w++) {
            a0 += red_s[0][w]; a1 += red_s[1][w];
            a2 += red_s[2][w]; a3 += red_s[3][w];
        }
        atomicAdd(&g_stats[0], a0);
        atomicAdd(&g_stats[1], a1);
        atomicAdd(&g_stats[2], a2);
        atomicAdd(&g_stats[3], a3);

        __threadfence();
        unsigned tk = atomicAdd(&g_ticket, 1u);
        if (tk == GRID2 - 1) {               // last block: fold stats, release
            const double nr = (double)N_NODES * 31.0;
            const double nc = (double)N_NODES * 64.0;
            double mr = g_stats[0] / nr;
            double vr = g_stats[1] / nr - mr * mr;
            double mc = g_stats[2] / nc;
            double vc = g_stats[3] / nc - mc * mc;
            float rscale = g_row[0] * rsqrtf((float)vr + 1e-5f);
            float cscale = g_col[0] * rsqrtf((float)vc + 1e-5f);
            g_bn = make_float4(rscale,
                               beta_row[0] - (float)mr * rscale,
                               cscale,
                               beta_col[0] - (float)mc * cscale);
            __threadfence();
            atomicExch(&g_flag, 1u);
        }
        // grid-wide spin until BN constants published
        while (atomicAdd(&g_flag, 0u) == 0u) {
            __nanosleep(64);
        }
        __threadfence();
        bn_sh = g_bn;
    }
    __syncthreads();

    // ---- phase 2: BN affine + relu, re-walk nodes with known layout ----
    const float rsc = bn_sh.x, rbi = bn_sh.y;
    const float csc = bn_sh.z, cbi = bn_sh.w;

    for (int n = warp_global; n < N_NODES; n += NWARPS2) {
        size_t rb = (size_t)n * OUT_C;
        if (lane < 31) {
            float v = out[rb + lane];
            out[rb + lane] = fmaxf(fmaf(v, rsc, rbi), 0.f);
        }
        size_t cb = rb + 31 + lane * 2;
        float v0 = out[cb], v1 = out[cb + 1];
        out[cb]     = fmaxf(fmaf(v0, csc, cbi), 0.f);
        out[cb + 1] = fmaxf(fmaf(v1, csc, cbi), 0.f);
    }
}

// =========================================================================
extern "C" void kernel_launch(void* const* d_in, const int* in_sizes, int n_in,
                              void* d_out, int out_size)
{
    const float* h        = (const float*)d_in[0];
    const float* W_fc     = (const float*)d_in[1];
    const float* a_attn   = (const float*)d_in[2];
    const float* w_row    = (const float*)d_in[3];
    const float* b_row    = (const float*)d_in[4];
    const float* w_col    = (const float*)d_in[5];
    const float* b_col    = (const float*)d_in[6];
    const float* g_row    = (const float*)d_in[7];
    const float* beta_row = (const float*)d_in[8];
    const float* g_col    = (const float*)d_in[9];
    const float* beta_col = (const float*)d_in[10];
    const int*   src_idx  = (const int*)d_in[11];
    float* out = (float*)d_out;

    const int smem1 = (128 * WSTRIDE + 128 * 34) * sizeof(float);   // 52224 B
    static bool attr_set = false;  // idempotent attribute set, not work state
    if (!attr_set) {
        cudaFuncSetAttribute(k1_gemm, cudaFuncAttributeMaxDynamicSharedMemorySize, smem1);
        attr_set = true;
    }

    k1_gemm<<<N_NODES / 32, 128, smem1>>>(h, W_fc, a_attn, w_row);
    k2_fused<<<GRID2, 256>>>(src_idx, w_col, b_row, b_col,
                             g_row, beta_row, g_col, beta_col, out);
}

// round 17
// speedup vs baseline: 1.0684x; 1.0684x over previous
#include <cuda_runtime.h>
#include <cuda_fp16.h>

#define N_NODES 65536
#define K_NBR   32
#define IN_DIM  128
#define D_DIM   64
#define OUT_C   95   // 31 row + 64 col

#define GRID2   608                 // 4 blocks/SM x 152 SMs = one full wave
#define WARPS2  8
#define NWARPS2 (GRID2 * WARPS2)    // 4864
#define TOTAL_F4 (N_NODES * OUT_C / 4)      // 1,556,480
#define F4_PER_THREAD (TOTAL_F4 / (GRID2 * 256))  // exactly 10

// ---------------- device scratch (no cudaMalloc allowed) ----------------
__device__ __half2 g_zh[N_NODES * 32];        // z in fp16, 8 MB (col path)
__device__ float4  g_sp[N_NODES];             // {e_src, p0, p1, 0}
__device__ float   g_edst[N_NODES];
__device__ double  g_stats[4];                // row_sum, row_ss, col_sum, col_ss
__device__ float4  g_bn;                      // {rscale, rbias, cscale, cbias}
__device__ unsigned g_ticket;                 // last-block detector
__device__ unsigned g_flag;                   // BN-ready release flag

// ---------------- f32x2 packed helpers (sm_103a) ----------------
__device__ __forceinline__ unsigned long long pack2(float lo, float hi) {
    unsigned long long r;
    asm("mov.b64 %0,{%1,%2};" : "=l"(r) : "f"(lo), "f"(hi));
    return r;
}
__device__ __forceinline__ unsigned long long fma2(unsigned long long a,
                                                   unsigned long long b,
                                                   unsigned long long c) {
    unsigned long long d;
    asm("fma.rn.f32x2 %0,%1,%2,%3;" : "=l"(d) : "l"(a), "l"(b), "l"(c));
    return d;
}
__device__ __forceinline__ float2 unpack2(unsigned long long v) {
    float2 f;
    asm("mov.b64 {%0,%1},%2;" : "=f"(f.x), "=f"(f.y) : "l"(v));
    return f;
}

#define WSTRIDE 68   // w_s row stride
#define HSTRIDE 66   // h_s row stride (64 rows + pad 2, 2-way conflict max)

// =========================================================================
// Kernel 1: z = h @ W_fc^T with packed f32x2 FMA. 64 rows/block,
// 256 threads (16 cg x 16 rg, 4 rows/thread). Halves W L2 re-reads.
// Block 0 zeroes stats/ticket/flag.
// =========================================================================
__global__ __launch_bounds__(256) void k1_gemm(
    const float* __restrict__ h,
    const float* __restrict__ W,       // [64,128] row-major
    const float* __restrict__ a_attn,  // [128]
    const float* __restrict__ w_row)   // [2,64]
{
    extern __shared__ float smem[];
    float* w_s = smem;                       // [128][WSTRIDE]
    float* h_s = smem + 128 * WSTRIDE;       // [128][HSTRIDE]

    const int t    = threadIdx.x;
    const int base = blockIdx.x * 64;

    if (blockIdx.x == 0) {
        if (t < 4) g_stats[t] = 0.0;
        if (t == 4) g_ticket = 0u;
        if (t == 5) g_flag = 0u;
    }

    // transpose-load W: w_s[i*WSTRIDE + d] = W[d*128 + i] (read coalesced)
    #pragma unroll
    for (int idx = t; idx < 64 * 128; idx += 256) {
        int d = idx >> 7, i = idx & 127;
        w_s[i * WSTRIDE + d] = W[idx];
    }

    // h tile transposed: h_s[c*HSTRIDE + r] = h[(base+r)*128 + c]
    #pragma unroll
    for (int idx = t; idx < 64 * 128; idx += 256) {
        int r = idx >> 7, c = idx & 127;
        h_s[c * HSTRIDE + r] = h[(size_t)(base + r) * IN_DIM + c];
    }
    __syncthreads();

    const int cg = t & 15;        // 4 cols each
    const int rg = t >> 4;        // 16 groups x 4 rows
    const int r0 = rg * 4;

    unsigned long long accA[4] = {0, 0, 0, 0};
    unsigned long long accB[4] = {0, 0, 0, 0};

    #pragma unroll 8
    for (int k = 0; k < 128; k++) {
        float4 w = *(const float4*)&w_s[k * WSTRIDE + cg * 4];
        unsigned long long hA = *(const unsigned long long*)&h_s[k * HSTRIDE + r0];
        unsigned long long hB = *(const unsigned long long*)&h_s[k * HSTRIDE + r0 + 2];
        unsigned long long w0 = pack2(w.x, w.x);
        unsigned long long w1 = pack2(w.y, w.y);
        unsigned long long w2 = pack2(w.z, w.z);
        unsigned long long w3 = pack2(w.w, w.w);
        accA[0] = fma2(w0, hA, accA[0]);  accB[0] = fma2(w0, hB, accB[0]);
        accA[1] = fma2(w1, hA, accA[1]);  accB[1] = fma2(w1, hB, accB[1]);
        accA[2] = fma2(w2, hA, accA[2]);  accB[2] = fma2(w2, hB, accB[2]);
        accA[3] = fma2(w3, hA, accA[3]);  accB[3] = fma2(w3, hB, accB[3]);
    }

    float rv[4][4];
    #pragma unroll
    for (int j = 0; j < 4; j++) {
        float2 uA = unpack2(accA[j]);
        float2 uB = unpack2(accB[j]);
        rv[0][j] = uA.x; rv[1][j] = uA.y;
        rv[2][j] = uB.x; rv[3][j] = uB.y;
    }

    #pragma unroll
    for (int r = 0; r < 4; r++) {
        int n = base + r0 + r;
        __half2 p0 = __floats2half2_rn(rv[r][0], rv[r][1]);
        __half2 p1 = __floats2half2_rn(rv[r][2], rv[r][3]);
        uint2 pk = make_uint2(*(unsigned*)&p0, *(unsigned*)&p1);
        *(uint2*)&g_zh[(size_t)n * 32 + cg * 2] = pk;
    }

    float4 va0 = *(const float4*)&a_attn[cg * 4];
    float4 va1 = *(const float4*)&a_attn[64 + cg * 4];
    float4 vw0 = *(const float4*)&w_row[cg * 4];
    float4 vw1 = *(const float4*)&w_row[64 + cg * 4];

    float ps[16];
    #pragma unroll
    for (int r = 0; r < 4; r++) {
        ps[r*4+0] = rv[r][0]*va0.x + rv[r][1]*va0.y + rv[r][2]*va0.z + rv[r][3]*va0.w;
        ps[r*4+1] = rv[r][0]*va1.x + rv[r][1]*va1.y + rv[r][2]*va1.z + rv[r][3]*va1.w;
        ps[r*4+2] = rv[r][0]*vw0.x + rv[r][1]*vw0.y + rv[r][2]*vw0.z + rv[r][3]*vw0.w;
        ps[r*4+3] = rv[r][0]*vw1.x + rv[r][1]*vw1.y + rv[r][2]*vw1.z + rv[r][3]*vw1.w;
    }
    #pragma unroll
    for (int off = 8; off; off >>= 1) {
        #pragma unroll
        for (int j = 0; j < 16; j++)
            ps[j] += __shfl_down_sync(0xffffffffu, ps[j], off, 16);
    }
    if (cg == 0) {
        #pragma unroll
        for (int r = 0; r < 4; r++) {
            int n = base + r0 + r;
            g_sp[n]   = make_float4(ps[r*4+0], ps[r*4+2], ps[r*4+3], 0.f);
            g_edst[n] = ps[r*4+1];
        }
    }
}

// =========================================================================
// Kernel 2 (fused, persistent single wave). Round-14 byte-exact (best).
// =========================================================================
__global__ __launch_bounds__(256, 4) void k2_fused(
    const int*   __restrict__ src_idx,
    const float* __restrict__ w_col,    // [32,64]
    const float* __restrict__ b_row_p,
    const float* __restrict__ b_col_p,
    const float* __restrict__ g_row,
    const float* __restrict__ beta_row,
    const float* __restrict__ g_col,
    const float* __restrict__ beta_col,
    float*       __restrict__ out)
{
    __shared__ __align__(16) __half2 wc_h[K_NBR * 32];  // [kk][lane], 4 KB
    __shared__ float red_s[4][WARPS2];
    __shared__ float4 bn_sh;

    const int t = threadIdx.x;
    const float2* wcg = (const float2*)w_col;
    #pragma unroll
    for (int i = t; i < K_NBR * 32; i += 256) {
        float2 w2 = wcg[i];
        wc_h[i] = __floats2half2_rn(w2.x, w2.y);
    }
    __syncthreads();

    const int lane = t & 31;
    const int wid  = t >> 5;
    const float b_row = b_row_p[0];
    const float b_col = b_col_p[0];

    float rs = 0.f, rss = 0.f, cs = 0.f, css = 0.f;

    const int warp_global = blockIdx.x * WARPS2 + wid;

    for (int n = warp_global; n < N_NODES; n += NWARPS2) {
        const int s = src_idx[n * K_NBR + lane];
        const float4 sp = g_sp[s];                    // {e_src, p0, p1, _}
        float e = sp.x + g_edst[n];
        e = fmaxf(e, 0.f) + 0.01f * fminf(e, 0.f);    // leaky relu

        // softmax without max-shift: |e| bounded (~6), exp fp32-safe
        float ex = __expf(e);
        float sum = ex;
        #pragma unroll
        for (int o = 16; o; o >>= 1) sum += __shfl_xor_sync(0xffffffffu, sum, o);
        const float alpha = __fdividef(ex, sum);

        // row conv
        float t0  = alpha * sp.y;
        float t1  = alpha * sp.z;
        float t1n = __shfl_down_sync(0xffffffffu, t1, 1);
        if (lane < 31) {
            float rv = t0 + t1n + b_row;
            out[(size_t)n * OUT_C + lane] = rv;
            rs += rv; rss += rv * rv;
        }

        // col conv: half2 product z*w (HMUL2), fp32 alpha*acc
        float2 acc = make_float2(0.f, 0.f);
        #pragma unroll 8
        for (int kk = 0; kk < K_NBR; kk++) {
            float a_k = __shfl_sync(0xffffffffu, alpha, kk);
            int   s_k = __shfl_sync(0xffffffffu, s, kk);
            __half2 zh = g_zh[(size_t)s_k * 32 + lane];
            __half2 pw = __hmul2(zh, wc_h[kk * 32 + lane]);
            float2 pf = __half22float2(pw);
            acc.x = fmaf(a_k, pf.x, acc.x);
            acc.y = fmaf(a_k, pf.y, acc.y);
        }
        float c0 = acc.x + b_col, c1 = acc.y + b_col;
        size_t ob = (size_t)n * OUT_C + 31 + lane * 2;
        out[ob]     = c0;
        out[ob + 1] = c1;
        cs  += c0 + c1;
        css += c0 * c0 + c1 * c1;
    }

    // ---- block-reduce stats ----
    #pragma unroll
    for (int o = 16; o; o >>= 1) {
        rs  += __shfl_xor_sync(0xffffffffu, rs,  o);
        rss += __shfl_xor_sync(0xffffffffu, rss, o);
        cs  += __shfl_xor_sync(0xffffffffu, cs,  o);
        css += __shfl_xor_sync(0xffffffffu, css, o);
    }
    if (lane == 0) {
        red_s[0][wid] = rs; red_s[1][wid] = rss;
        red_s[2][wid] = cs; red_s[3][wid] = css;
    }
    __syncthreads();
    if (t == 0) {
        double a0 = 0, a1 = 0, a2 = 0, a3 = 0;
        #pragma unroll
        for (int w = 0; w < WARPS2; w++) {
            a0 += red_s[0][w]; a1 += red_s[1][w];
            a2 += red_s[2][w]; a3 += red_s[3][w];
        }
        atomicAdd(&g_stats[0], a0);
        atomicAdd(&g_stats[1], a1);
        atomicAdd(&g_stats[2], a2);
        atomicAdd(&g_stats[3], a3);

        __threadfence();
        unsigned tk = atomicAdd(&g_ticket, 1u);
        if (tk == GRID2 - 1) {               // last block: fold stats, release
            const double nr = (double)N_NODES * 31.0;
            const double nc = (double)N_NODES * 64.0;
            double mr = g_stats[0] / nr;
            double vr = g_stats[1] / nr - mr * mr;
            double mc = g_stats[2] / nc;
            double vc = g_stats[3] / nc - mc * mc;
            float rscale = g_row[0] * rsqrtf((float)vr + 1e-5f);
            float cscale = g_col[0] * rsqrtf((float)vc + 1e-5f);
            g_bn = make_float4(rscale,
                               beta_row[0] - (float)mr * rscale,
                               cscale,
                               beta_col[0] - (float)mc * cscale);
            __threadfence();
            atomicExch(&g_flag, 1u);
        }
        // grid-wide spin until BN constants published
        while (atomicAdd(&g_flag, 0u) == 0u) {
            __nanosleep(64);
        }
        __threadfence();
        bn_sh = g_bn;
    }
    __syncthreads();

    // ---- phase 2: BN affine + relu in place, exactly 10 f4/thread ----
    const float rsc = bn_sh.x, rbi = bn_sh.y;
    const float csc = bn_sh.z, cbi = bn_sh.w;

    float4* o4 = (float4*)out;
    const int gtid = blockIdx.x * 256 + t;
    #pragma unroll
    for (int j = 0; j < F4_PER_THREAD; j++) {
        int i = gtid + j * (GRID2 * 256);
        float4 v = o4[i];
        int r = (i * 4) % OUT_C;
        float f[4] = {v.x, v.y, v.z, v.w};
        #pragma unroll
        for (int q = 0; q < 4; q++) {
            int c = r + q; c = (c >= OUT_C) ? c - OUT_C : c;
            float sc = (c < 31) ? rsc : csc;
            float bi = (c < 31) ? rbi : cbi;
            f[q] = fmaxf(fmaf(f[q], sc, bi), 0.f);
        }
        o4[i] = make_float4(f[0], f[1], f[2], f[3]);
    }
}

// =========================================================================
extern "C" void kernel_launch(void* const* d_in, const int* in_sizes, int n_in,
                              void* d_out, int out_size)
{
    const float* h        = (const float*)d_in[0];
    const float* W_fc     = (const float*)d_in[1];
    const float* a_attn   = (const float*)d_in[2];
    const float* w_row    = (const float*)d_in[3];
    const float* b_row    = (const float*)d_in[4];
    const float* w_col    = (const float*)d_in[5];
    const float* b_col    = (const float*)d_in[6];
    const float* g_row    = (const float*)d_in[7];
    const float* beta_row = (const float*)d_in[8];
    const float* g_col    = (const float*)d_in[9];
    const float* beta_col = (const float*)d_in[10];
    const int*   src_idx  = (const int*)d_in[11];
    float* out = (float*)d_out;

    const int smem1 = (128 * WSTRIDE + 128 * HSTRIDE) * sizeof(float);  // 68608 B
    static bool attr_set = false;  // idempotent attribute set, not work state
    if (!attr_set) {
        cudaFuncSetAttribute(k1_gemm, cudaFuncAttributeMaxDynamicSharedMemorySize, smem1);
        attr_set = true;
    }

    k1_gemm<<<N_NODES / 64, 256, smem1>>>(h, W_fc, a_attn, w_row);
    k2_fused<<<GRID2, 256>>>(src_idx, w_col, b_row, b_col,
                             g_row, beta_row, g_col, beta_col, out);
}